// round 5
// baseline (speedup 1.0000x reference)
#include <cuda_runtime.h>
#include <cstdint>

// out[c] = sum_{i,j} w[i,j,c] * inputs[0,i,j,c];  H=W=512, C=256 (batch 0 only).
// 512 MB streaming read. Per-thread cp.async pipelines into SMEM: MLP lives in
// SMEM instead of registers -> full 64-warp occupancy + 192KB/SM in flight.

#define NCHUNK  65536      // 4KB chunks per stream (256 MB / 4KB)
#define GRID    1184       // 148 SMs x 8 blocks, single wave
#define STAGES  3
#define THREADS 256

__global__ void zero_out_kernel(float* out) { out[threadIdx.x] = 0.0f; }

__device__ __forceinline__ void cp16(uint32_t smem_dst, const void* gsrc) {
    asm volatile("cp.async.cg.shared.global [%0], [%1], 16;"
                 :: "r"(smem_dst), "l"(gsrc) : "memory");
}
__device__ __forceinline__ void cp_commit() {
    asm volatile("cp.async.commit_group;" ::: "memory");
}
template <int N>
__device__ __forceinline__ void cp_wait() {
    asm volatile("cp.async.wait_group %0;" :: "n"(N) : "memory");
}

__global__ __launch_bounds__(THREADS, 8)
void chan_dot_cpasync(const float4* __restrict__ in,
                      const float4* __restrict__ w,
                      float* __restrict__ out)
{
    __shared__ float4 sa[STAGES][THREADS];
    __shared__ float4 sb[STAGES][THREADS];

    const int tid = threadIdx.x;
    const int tx  = tid & 63;          // channel quad (chunk is 256 f4 -> idx%64 == tid%64... )
    const int ty  = tid >> 6;

    const uint32_t sa_base = (uint32_t)__cvta_generic_to_shared(&sa[0][tid]);
    const uint32_t sb_base = (uint32_t)__cvta_generic_to_shared(&sb[0][tid]);
    const uint32_t stage_stride = THREADS * 16;   // bytes per stage

    // Prologue: fill STAGES stages. Chunk c covers float4 [c*256, c*256+256);
    // this thread owns element c*256 + tid (channel quad = tid & 63).
    int c = blockIdx.x;
    #pragma unroll
    for (int s = 0; s < STAGES; s++) {
        if (c < NCHUNK) {
            const int i4 = c * THREADS + tid;
            cp16(sa_base + s * stage_stride, in + i4);
            cp16(sb_base + s * stage_stride, w  + i4);
        }
        cp_commit();
        c += GRID;
    }

    float ax = 0.f, ay = 0.f, az = 0.f, aw = 0.f;

    int it = 0;
    for (int cur = blockIdx.x; cur < NCHUNK; cur += GRID, it++) {
        cp_wait<STAGES - 1>();             // oldest group (this slot) complete
        const int s = it % STAGES;
        const float4 a = *(const float4*)&sa[s][tid];
        const float4 b = *(const float4*)&sb[s][tid];
        ax = fmaf(a.x, b.x, ax);
        ay = fmaf(a.y, b.y, ay);
        az = fmaf(a.z, b.z, az);
        aw = fmaf(a.w, b.w, aw);

        // Refill this slot with chunk cur + STAGES*GRID (issued after the read).
        const int cn = cur + STAGES * GRID;
        if (cn < NCHUNK) {
            const int i4 = cn * THREADS + tid;
            cp16(sa_base + s * stage_stride, in + i4);
            cp16(sb_base + s * stage_stride, w  + i4);
        }
        cp_commit();
    }
    cp_wait<0>();

    // Block reduction: 4 ty-lanes per channel quad, then atomics (1184/chan).
    __shared__ float4 red[4][64];
    red[ty][tx] = make_float4(ax, ay, az, aw);
    __syncthreads();
    if (ty == 0) {
        const float4 t0 = red[0][tx];
        const float4 t1 = red[1][tx];
        const float4 t2 = red[2][tx];
        const float4 t3 = red[3][tx];
        atomicAdd(&out[tx * 4 + 0], (t0.x + t1.x) + (t2.x + t3.x));
        atomicAdd(&out[tx * 4 + 1], (t0.y + t1.y) + (t2.y + t3.y));
        atomicAdd(&out[tx * 4 + 2], (t0.z + t1.z) + (t2.z + t3.z));
        atomicAdd(&out[tx * 4 + 3], (t0.w + t1.w) + (t2.w + t3.w));
    }
}

extern "C" void kernel_launch(void* const* d_in, const int* in_sizes, int n_in,
                              void* d_out, int out_size) {
    const float4* in = (const float4*)d_in[0];   // (2,512,512,256) f32; batch 0 only
    const float4* w  = (const float4*)d_in[1];   // (512,512,256) f32
    float* out = (float*)d_out;                  // 256 f32

    zero_out_kernel<<<1, 256>>>(out);
    chan_dot_cpasync<<<GRID, THREADS>>>(in, w, out);
}